// round 10
// baseline (speedup 1.0000x reference)
#include <cuda_runtime.h>
#include <cuda_bf16.h>
#include <math.h>

// ---------------------------------------------------------------------------
// DeepJ biaxial LSTM.  B=1024, N=48, TU=256, NU=128, IN_T=50 (pad 64).
//   - time-axis layers: single step h=c=0 => feed-forward gate GEMMs on
//     mma.sync m16n8k16 bf16 with 3xK hi/lo split (A'=[Ah|Al|Ah],
//     B'=[Wh|Wh|Wl]); N-tile 128 to halve A re-reads.
//   - note-axis scan: NOW TENSORIZED.  64 persistent blocks x 16 batches;
//     recurrent GEMMs (M16 x N512 x K'384) on mma.sync bf16 3x-split,
//     weights streamed L2->smem; pointwise/state/output scalar fp32.
// ---------------------------------------------------------------------------

#define BB 1024
#define NN 48
#define MM (BB * NN)   // 49152

typedef __nv_bfloat16 bf16;

// scratch (device globals: allocation-free)
__device__ bf16  g_ac0[MM * 192];      // rnn_in split-concat (K'=192)
__device__ bf16  g_ac1[MM * 768];      // h1 split-concat     (K'=768)
__device__ bf16  g_ac2[MM * 768];      // feats split-concat  (K'=768)
__device__ float g_raw[MM * 768];      // raw gate scratch
__device__ bf16  g_w0c[768 * 192];     // t_Wih0 live-gate split-concat
__device__ bf16  g_w1c[768 * 768];     // t_Wih1 live-gate split-concat
__device__ bf16  g_w2c[512 * 768];     // n_Wih0[:, :256] split-concat
__device__ float g_wc[512];            // n_Wih0[:, 256] (cond column)
__device__ float g_xw[MM * 512];
__device__ bf16  g_swh0[512 * 384];    // n_Whh0 split-concat (scan)
__device__ bf16  g_swi1[512 * 384];    // n_Wih1 split-concat (scan)
__device__ bf16  g_swh1[512 * 384];    // n_Whh1 split-concat (scan)

__device__ __forceinline__ float sigf(float x) { return 1.0f / (1.0f + expf(-x)); }

// ----------------------------- prep kernels -------------------------------

__device__ __forceinline__ void split3(float v, bf16* p0, bf16* p1, bf16* p2) {
    bf16 hh = __float2bfloat16(v);
    bf16 hl = __float2bfloat16(v - __bfloat162float(hh));
    *p0 = hh; *p1 = hl; *p2 = hh;          // activations: [hi | lo | hi]
}
__device__ __forceinline__ void splitw(float v, bf16* p0, bf16* p1, bf16* p2) {
    bf16 hh = __float2bfloat16(v);
    bf16 hl = __float2bfloat16(v - __bfloat162float(hh));
    *p0 = hh; *p1 = hh; *p2 = hl;          // weights: [hi | hi | lo]
}

__global__ void build_ac0(const float* __restrict__ note) {
    int idx = blockIdx.x * blockDim.x + threadIdx.x;   // MM * 64
    if (idx >= MM * 64) return;
    int f = idx & 63;
    int m = idx >> 6;
    int b = m / NN, n = m % NN;
    float v = 0.0f;
    if (f == 0) {
        v = (float)n * (1.0f / (float)NN);
    } else if (f < 13) {
        v = ((f - 1) == (n % 12)) ? 1.0f : 0.0f;
    } else if (f < 38) {
        int p = n + (f - 13) - 12;
        v = (p >= 0 && p < NN) ? note[b * NN + p] : 0.0f;
    } else if (f < 50) {
        const float* nb = note + b * NN + (f - 38) * 4;
        v = nb[0] + nb[1] + nb[2] + nb[3];
    }
    size_t o = (size_t)m * 192 + f;
    split3(v, &g_ac0[o], &g_ac0[o + 64], &g_ac0[o + 128]);
}

__global__ void build_w0c(const float* __restrict__ w) {   // (1024 x 50)
    int idx = blockIdx.x * blockDim.x + threadIdx.x;       // 768 * 64
    if (idx >= 768 * 64) return;
    int k = idx & 63, r = idx >> 6;
    int u = r & 255, g3 = r >> 8;
    int ga = (g3 == 0) ? 0 : g3 + 1;
    float v = (k < 50) ? w[(size_t)(ga * 256 + u) * 50 + k] : 0.0f;
    size_t o = (size_t)r * 192 + k;
    splitw(v, &g_w0c[o], &g_w0c[o + 64], &g_w0c[o + 128]);
}

__global__ void build_w1c(const float* __restrict__ w) {   // (1024 x 256)
    int idx = blockIdx.x * blockDim.x + threadIdx.x;       // 768 * 256
    if (idx >= 768 * 256) return;
    int k = idx & 255, r = idx >> 8;
    int u = r & 255, g3 = r >> 8;
    int ga = (g3 == 0) ? 0 : g3 + 1;
    float v = w[(size_t)(ga * 256 + u) * 256 + k];
    size_t o = (size_t)r * 768 + k;
    splitw(v, &g_w1c[o], &g_w1c[o + 256], &g_w1c[o + 512]);
}

__global__ void build_w2c(const float* __restrict__ w) {   // n_Wih0 (512 x 257)
    int idx = blockIdx.x * blockDim.x + threadIdx.x;       // 512 * 256
    if (idx >= 512 * 256) return;
    int k = idx & 255, r = idx >> 8;
    float v = w[(size_t)r * 257 + k];
    size_t o = (size_t)r * 768 + k;
    splitw(v, &g_w2c[o], &g_w2c[o + 256], &g_w2c[o + 512]);
    if (k == 0) g_wc[r] = w[(size_t)r * 257 + 256];
}

// scan weight (512 x 128) -> split-concat bf16 (512 x 384)
__global__ void build_wsc(const float* __restrict__ w, bf16* __restrict__ dst) {
    int idx = blockIdx.x * blockDim.x + threadIdx.x;       // 512 * 128
    if (idx >= 512 * 128) return;
    int k = idx & 127, r = idx >> 7;
    float v = w[(size_t)r * 128 + k];
    size_t o = (size_t)r * 384 + k;
    splitw(v, &dst[o], &dst[o + 128], &dst[o + 256]);
}

// pointwise: raw gates (i,g,o blocks of 256) -> h, emitted split-concat bf16
__global__ void act_kernel(const float* __restrict__ raw,
                           const float* __restrict__ b,
                           bf16* __restrict__ ac) {
    int idx = blockIdx.x * blockDim.x + threadIdx.x;   // MM * 256
    if (idx >= MM * 256) return;
    int u = idx & 255;
    size_t m = (size_t)(idx >> 8);
    float gi = raw[m * 768 + u]       + b[u];
    float gg = raw[m * 768 + 256 + u] + b[512 + u];
    float go = raw[m * 768 + 512 + u] + b[768 + u];
    float h = sigf(go) * tanhf(sigf(gi) * tanhf(gg));
    size_t o = m * 768 + u;
    split3(h, &ac[o], &ac[o + 256], &ac[o + 512]);
}

// ------------------------- bf16 mma.sync gate GEMM ------------------------
// C[M x N] = A'[M x K'] @ B'[N x K']^T.  Block tile 128 x 128, 8 warps
// (4m x 2n), K chunks of 32.  Staging [row][k] stride 40 bf16.

__device__ __forceinline__ void mma16(float c[4], const unsigned a[4],
                                      const unsigned b[2]) {
    asm volatile(
        "mma.sync.aligned.m16n8k16.row.col.f32.bf16.bf16.f32 "
        "{%0,%1,%2,%3}, {%4,%5,%6,%7}, {%8,%9}, {%0,%1,%2,%3};"
        : "+f"(c[0]), "+f"(c[1]), "+f"(c[2]), "+f"(c[3])
        : "r"(a[0]), "r"(a[1]), "r"(a[2]), "r"(a[3]), "r"(b[0]), "r"(b[1]));
}

__global__ __launch_bounds__(256)
void gemm_bf(const bf16* __restrict__ A, const bf16* __restrict__ B,
             float* __restrict__ C, int Kp, int ldc) {
    extern __shared__ char smem[];
    bf16* sA = (bf16*)smem;                  // [128][40]
    bf16* sB = (bf16*)(smem + 10240);        // [128][40]

    const int t = threadIdx.x;
    const int lane = t & 31, wid = t >> 5;
    const int wm = wid & 3, wn = wid >> 2;
    const int gid = lane >> 2, tid4 = lane & 3;
    const int m0 = blockIdx.x * 128;
    const int c0 = blockIdx.y * 128;

    float acc[2][8][4];
#pragma unroll
    for (int mi = 0; mi < 2; mi++)
#pragma unroll
        for (int ni = 0; ni < 8; ni++)
#pragma unroll
            for (int q = 0; q < 4; q++) acc[mi][ni][q] = 0.0f;

    const int r0 = t >> 2, cc0 = (t & 3) * 8;   // loader: 2 slots each for A,B

    uint4 pa0, pa1, pb0, pb1;
    pa0 = *(const uint4*)(A + (size_t)(m0 + r0) * Kp + cc0);
    pa1 = *(const uint4*)(A + (size_t)(m0 + r0 + 64) * Kp + cc0);
    pb0 = *(const uint4*)(B + (size_t)(c0 + r0) * Kp + cc0);
    pb1 = *(const uint4*)(B + (size_t)(c0 + r0 + 64) * Kp + cc0);

    const int nchunks = Kp >> 5;
    for (int kc = 0; kc < nchunks; kc++) {
        *(uint4*)&sA[r0 * 40 + cc0]        = pa0;
        *(uint4*)&sA[(r0 + 64) * 40 + cc0] = pa1;
        *(uint4*)&sB[r0 * 40 + cc0]        = pb0;
        *(uint4*)&sB[(r0 + 64) * 40 + cc0] = pb1;
        __syncthreads();

        if (kc + 1 < nchunks) {
            int ko = (kc + 1) * 32;
            pa0 = *(const uint4*)(A + (size_t)(m0 + r0) * Kp + ko + cc0);
            pa1 = *(const uint4*)(A + (size_t)(m0 + r0 + 64) * Kp + ko + cc0);
            pb0 = *(const uint4*)(B + (size_t)(c0 + r0) * Kp + ko + cc0);
            pb1 = *(const uint4*)(B + (size_t)(c0 + r0 + 64) * Kp + ko + cc0);
        }

#pragma unroll
        for (int kh = 0; kh < 2; kh++) {
            const int kb = kh * 16;
            unsigned Af[2][4], Bf[8][2];
#pragma unroll
            for (int mi = 0; mi < 2; mi++) {
                int r = wm * 32 + mi * 16 + gid;
                Af[mi][0] = *(const unsigned*)&sA[r * 40 + kb + tid4 * 2];
                Af[mi][1] = *(const unsigned*)&sA[(r + 8) * 40 + kb + tid4 * 2];
                Af[mi][2] = *(const unsigned*)&sA[r * 40 + kb + tid4 * 2 + 8];
                Af[mi][3] = *(const unsigned*)&sA[(r + 8) * 40 + kb + tid4 * 2 + 8];
            }
#pragma unroll
            for (int ni = 0; ni < 8; ni++) {
                int c = wn * 64 + ni * 8 + gid;
                Bf[ni][0] = *(const unsigned*)&sB[c * 40 + kb + tid4 * 2];
                Bf[ni][1] = *(const unsigned*)&sB[c * 40 + kb + tid4 * 2 + 8];
            }
#pragma unroll
            for (int mi = 0; mi < 2; mi++)
#pragma unroll
                for (int ni = 0; ni < 8; ni++)
                    mma16(acc[mi][ni], Af[mi], Bf[ni]);
        }
        __syncthreads();
    }

    // dump accumulators to smem [128][132], then coalesced float4 stores
    float* sd = (float*)smem;
#pragma unroll
    for (int mi = 0; mi < 2; mi++)
#pragma unroll
        for (int ni = 0; ni < 8; ni++) {
            int r = wm * 32 + mi * 16 + gid;
            int c = wn * 64 + ni * 8 + tid4 * 2;
            sd[r * 132 + c]           = acc[mi][ni][0];
            sd[r * 132 + c + 1]       = acc[mi][ni][1];
            sd[(r + 8) * 132 + c]     = acc[mi][ni][2];
            sd[(r + 8) * 132 + c + 1] = acc[mi][ni][3];
        }
    __syncthreads();

#pragma unroll
    for (int j = 0; j < 16; j++) {
        int i = j * 256 + t;                 // 4096 float4 slots
        int r = i >> 5, c4 = i & 31;
        *(float4*)&C[(size_t)(m0 + r) * ldc + c0 + c4 * 4] =
            *(float4*)&sd[r * 132 + c4 * 4];
    }
}

// ------------------------- tensorized note-axis scan -----------------------
// 64 blocks x 16 batches, 256 threads (8 warps).  Per step, each recurrent
// GEMM is M16 x N512 x K'384 bf16 (3x split).  Warp wid owns gate columns
// [wid*64, wid*64+64).  Weights streamed L2->smem in 12 dbl-buffered chunks.
// smem: sW 81920 B | sH1 12544 | sH2 12544 | sG 33280 | sWo 512  = 140800 B

__device__ __forceinline__ void scan_pass(float acc[8][4],
                                          const bf16* __restrict__ W,
                                          const bf16* sH, bf16* sW,
                                          int t, int wid, int gid, int tid4) {
    const int wr = t >> 2, wk = (t & 3) * 8;
    uint4 pre[8];
#pragma unroll
    for (int i = 0; i < 8; i++)
        pre[i] = *(const uint4*)&W[(size_t)(wr + 64 * i) * 384 + wk];
#pragma unroll
    for (int i = 0; i < 8; i++)
        *(uint4*)&sW[(wr + 64 * i) * 40 + wk] = pre[i];
    __syncthreads();

    for (int c = 0; c < 12; c++) {
        const bf16* cur = sW + (c & 1) * 20480;
        if (c < 11) {
            int ko = (c + 1) * 32;
#pragma unroll
            for (int i = 0; i < 8; i++)
                pre[i] = *(const uint4*)&W[(size_t)(wr + 64 * i) * 384 + ko + wk];
        }
#pragma unroll
        for (int kh = 0; kh < 2; kh++) {
            const bf16* hrow = sH + gid * 392 + c * 32 + kh * 16 + tid4 * 2;
            unsigned Af[4];
            Af[0] = *(const unsigned*)hrow;
            Af[1] = *(const unsigned*)(hrow + 8 * 392);
            Af[2] = *(const unsigned*)(hrow + 8);
            Af[3] = *(const unsigned*)(hrow + 8 * 392 + 8);
#pragma unroll
            for (int ni = 0; ni < 8; ni++) {
                const bf16* wrow = cur + (wid * 64 + ni * 8 + gid) * 40
                                       + kh * 16 + tid4 * 2;
                unsigned Bf[2];
                Bf[0] = *(const unsigned*)wrow;
                Bf[1] = *(const unsigned*)(wrow + 8);
                mma16(acc[ni], Af, Bf);
            }
        }
        if (c < 11) {
            bf16* nxt = sW + ((c + 1) & 1) * 20480;
#pragma unroll
            for (int i = 0; i < 8; i++)
                *(uint4*)&nxt[(wr + 64 * i) * 40 + wk] = pre[i];
        }
        __syncthreads();
    }
}

__device__ __forceinline__ void acc_to_sG(const float acc[8][4], float* sG,
                                          int wid, int gid, int tid4) {
#pragma unroll
    for (int ni = 0; ni < 8; ni++) {
        int c = wid * 64 + ni * 8 + tid4 * 2;
        sG[gid * 520 + c]           = acc[ni][0];
        sG[gid * 520 + c + 1]       = acc[ni][1];
        sG[(gid + 8) * 520 + c]     = acc[ni][2];
        sG[(gid + 8) * 520 + c + 1] = acc[ni][3];
    }
}

__global__ __launch_bounds__(256, 1)
void scan_kernel(const float* __restrict__ targets,
                 const float* __restrict__ nb0,
                 const float* __restrict__ nb1,
                 const float* __restrict__ outW,
                 const float* __restrict__ outb,
                 float* __restrict__ out) {
    extern __shared__ char sm[];
    bf16*  sW  = (bf16*)sm;                    // 2 x 512 x 40
    bf16*  sH1 = (bf16*)(sm + 81920);          // 16 x 392
    bf16*  sH2 = (bf16*)(sm + 94464);          // 16 x 392
    float* sG  = (float*)(sm + 107008);        // 16 x 520
    float* sWo = (float*)(sm + 140288);        // 128

    const int t = threadIdx.x;
    const int lane = t & 31, wid = t >> 5;
    const int gid = lane >> 2, tid4 = lane & 3;
    const int u = t & 127, bp = t >> 7;        // pointwise mapping
    const int B0 = blockIdx.x * 16;

    if (t < 128) sWo[t] = outW[t];
    for (int i = t; i < 6272; i += 256) ((unsigned*)sH1)[i] = 0u; // sH1+sH2

    float c1[8], c2[8];
#pragma unroll
    for (int j = 0; j < 8; j++) { c1[j] = 0.0f; c2[j] = 0.0f; }
    float b0r[4], b1r[4], wcr[4];
#pragma unroll
    for (int g = 0; g < 4; g++) {
        b0r[g] = nb0[g * 128 + u];
        b1r[g] = nb1[g * 128 + u];
        wcr[g] = g_wc[g * 128 + u];
    }
    const float ob = outb[0];
    __syncthreads();

    for (int n = 0; n < NN; n++) {
        // ---- layer 0: gates = h1_prev @ Whh0^T ----
        float acc[8][4];
#pragma unroll
        for (int ni = 0; ni < 8; ni++)
#pragma unroll
            for (int q = 0; q < 4; q++) acc[ni][q] = 0.0f;
        scan_pass(acc, g_swh0, sH1, sW, t, wid, gid, tid4);
        acc_to_sG(acc, sG, wid, gid, tid4);
        __syncthreads();

        // pointwise L0 (thread = unit u, batches bp*8..bp*8+7)
#pragma unroll
        for (int j = 0; j < 8; j++) {
            int b = bp * 8 + j, bg = B0 + b;
            float cond = (n == 0) ? 0.0f : targets[bg * NN + n - 1];
            size_t m = (size_t)bg * NN + n;
            float gi = sG[b * 520 + u]       + g_xw[m * 512 + u]       + b0r[0] + cond * wcr[0];
            float gf = sG[b * 520 + 128 + u] + g_xw[m * 512 + 128 + u] + b0r[1] + cond * wcr[1];
            float gg = sG[b * 520 + 256 + u] + g_xw[m * 512 + 256 + u] + b0r[2] + cond * wcr[2];
            float go = sG[b * 520 + 384 + u] + g_xw[m * 512 + 384 + u] + b0r[3] + cond * wcr[3];
            float cc = sigf(gf) * c1[j] + sigf(gi) * tanhf(gg);
            c1[j] = cc;
            float h = sigf(go) * tanhf(cc);
            bf16 hh = __float2bfloat16(h);
            bf16 hl = __float2bfloat16(h - __bfloat162float(hh));
            sH1[b * 392 + u] = hh;
            sH1[b * 392 + 128 + u] = hl;
            sH1[b * 392 + 256 + u] = hh;
        }
        __syncthreads();

        // ---- layer 1: gates = h1 @ Wih1^T + h2_prev @ Whh1^T ----
#pragma unroll
        for (int ni = 0; ni < 8; ni++)
#pragma unroll
            for (int q = 0; q < 4; q++) acc[ni][q] = 0.0f;
        scan_pass(acc, g_swi1, sH1, sW, t, wid, gid, tid4);
        scan_pass(acc, g_swh1, sH2, sW, t, wid, gid, tid4);
        acc_to_sG(acc, sG, wid, gid, tid4);
        __syncthreads();

        // pointwise L1; h2 (fp32) parked in sG[b][u]
#pragma unroll
        for (int j = 0; j < 8; j++) {
            int b = bp * 8 + j;
            float gi = sG[b * 520 + u]       + b1r[0];
            float gf = sG[b * 520 + 128 + u] + b1r[1];
            float gg = sG[b * 520 + 256 + u] + b1r[2];
            float go = sG[b * 520 + 384 + u] + b1r[3];
            float cc = sigf(gf) * c2[j] + sigf(gi) * tanhf(gg);
            c2[j] = cc;
            float h = sigf(go) * tanhf(cc);
            bf16 hh = __float2bfloat16(h);
            bf16 hl = __float2bfloat16(h - __bfloat162float(hh));
            sH2[b * 392 + u] = hh;
            sH2[b * 392 + 128 + u] = hl;
            sH2[b * 392 + 256 + u] = hh;
            sG[b * 520 + u] = h;           // own (b,u) slot: no race
        }
        __syncthreads();

        // ---- output: warp wid -> batches 2*wid, 2*wid+1 (half-warps) ----
        {
            int b2 = 2 * wid + (lane >> 4), ul = lane & 15;
            float p = 0.0f;
#pragma unroll
            for (int j = 0; j < 8; j++)
                p += sG[b2 * 520 + ul + 16 * j] * sWo[ul + 16 * j];
#pragma unroll
            for (int off = 8; off; off >>= 1)
                p += __shfl_down_sync(0xffffffffu, p, off, 16);
            if (ul == 0) out[(B0 + b2) * NN + n] = sigf(p + ob);
        }
        // next layer-0 pass re-syncs before sG is overwritten
    }
}

// --------------------------------- launch ---------------------------------

extern "C" void kernel_launch(void* const* d_in, const int* in_sizes, int n_in,
                              void* d_out, int out_size) {
    (void)in_sizes; (void)n_in; (void)out_size;
    const float* note    = (const float*)d_in[0];
    const float* targets = (const float*)d_in[1];
    const float* tWih0   = (const float*)d_in[2];
    const float* tb0     = (const float*)d_in[4];
    const float* tWih1   = (const float*)d_in[5];
    const float* tb1     = (const float*)d_in[7];
    const float* nWih0   = (const float*)d_in[8];
    const float* nWhh0   = (const float*)d_in[9];
    const float* nb0     = (const float*)d_in[10];
    const float* nWih1   = (const float*)d_in[11];
    const float* nWhh1   = (const float*)d_in[12];
    const float* nb1     = (const float*)d_in[13];
    const float* outW    = (const float*)d_in[14];
    const float* outb    = (const float*)d_in[15];
    float* out = (float*)d_out;

    bf16 *p_ac0, *p_ac1, *p_ac2, *p_w0c, *p_w1c, *p_w2c;
    bf16 *p_swh0, *p_swi1, *p_swh1;
    float *p_raw, *p_xw;
    cudaGetSymbolAddress((void**)&p_ac0, g_ac0);
    cudaGetSymbolAddress((void**)&p_ac1, g_ac1);
    cudaGetSymbolAddress((void**)&p_ac2, g_ac2);
    cudaGetSymbolAddress((void**)&p_raw, g_raw);
    cudaGetSymbolAddress((void**)&p_w0c, g_w0c);
    cudaGetSymbolAddress((void**)&p_w1c, g_w1c);
    cudaGetSymbolAddress((void**)&p_w2c, g_w2c);
    cudaGetSymbolAddress((void**)&p_xw,  g_xw);
    cudaGetSymbolAddress((void**)&p_swh0, g_swh0);
    cudaGetSymbolAddress((void**)&p_swi1, g_swi1);
    cudaGetSymbolAddress((void**)&p_swh1, g_swh1);

    build_ac0<<<(MM * 64) / 256, 256>>>(note);
    build_w0c<<<(768 * 64) / 256, 256>>>(tWih0);
    build_w1c<<<(768 * 256) / 256, 256>>>(tWih1);
    build_w2c<<<(512 * 256) / 256, 256>>>(nWih0);
    build_wsc<<<(512 * 128) / 256, 256>>>(nWhh0, p_swh0);
    build_wsc<<<(512 * 128) / 256, 256>>>(nWih1, p_swi1);
    build_wsc<<<(512 * 128) / 256, 256>>>(nWhh1, p_swh1);

    const int smemG = 128 * 132 * (int)sizeof(float);   // 67584 (>= staging)
    cudaFuncSetAttribute(gemm_bf, cudaFuncAttributeMaxDynamicSharedMemorySize, smemG);

    // raw_g1 = rnn_in' @ w0c'^T     (K'=192, N=768)
    gemm_bf<<<dim3(384, 6), 256, smemG>>>(p_ac0, p_w0c, p_raw, 192, 768);
    act_kernel<<<(MM * 256) / 256, 256>>>(p_raw, tb0, p_ac1);
    // raw_g2 = h1' @ w1c'^T         (K'=768, N=768)
    gemm_bf<<<dim3(384, 6), 256, smemG>>>(p_ac1, p_w1c, p_raw, 768, 768);
    act_kernel<<<(MM * 256) / 256, 256>>>(p_raw, tb1, p_ac2);
    // g_xw = feats' @ w2c'^T        (K'=768, N=512, raw gates for the scan)
    gemm_bf<<<dim3(384, 4), 256, smemG>>>(p_ac2, p_w2c, p_xw, 768, 512);

    const int smemS = 140800;
    cudaFuncSetAttribute(scan_kernel, cudaFuncAttributeMaxDynamicSharedMemorySize, smemS);
    scan_kernel<<<64, 256, smemS>>>(targets, nb0, nb1, outW, outb, out);
}

// round 11
// speedup vs baseline: 1.0190x; 1.0190x over previous
#include <cuda_runtime.h>
#include <cuda_bf16.h>
#include <math.h>

// ---------------------------------------------------------------------------
// DeepJ biaxial LSTM.  B=1024, N=48, TU=256, NU=128, IN_T=50 (pad 64).
//   - time-axis layers: single step h=c=0 => feed-forward gate GEMMs on
//     mma.sync m16n8k8 tf32 3x-split with fused activation (R6, known-good).
//   - note-axis scan: tensorized (mma.sync bf16 3xK split), 64 persistent
//     blocks x 16 batches.  Weights stream L2->smem via a 4-stage cp.async
//     ring (3 groups in flight) so per-chunk cost is bandwidth, not latency.
// ---------------------------------------------------------------------------

#define BB 1024
#define NN 48
#define MM (BB * NN)   // 49152
#define K1 64          // IN_T=50 padded to 64

typedef __nv_bfloat16 bf16;

// scratch (device globals: allocation-free)
__device__ float g_rnnin[MM * K1];
__device__ float g_w0p[1024 * K1];     // padded t_Wih0
__device__ float g_w0i[768 * K1];      // interleaved 3-gate t_Wih0
__device__ float g_w1i[768 * 256];     // interleaved 3-gate t_Wih1
__device__ float g_h1[MM * 256];
__device__ float g_feats[MM * 256];
__device__ float g_w2p[512 * 256];     // n_Wih0[:, :256]
__device__ float g_wc[512];            // n_Wih0[:, 256] (cond column)
__device__ float g_xw[MM * 512];
__device__ __align__(16) bf16 g_wcat[3 * 512 * 384];  // scan weights, split-concat

__device__ __forceinline__ float sigf(float x) { return 1.0f / (1.0f + expf(-x)); }

__device__ __forceinline__ unsigned tf32r(float x) {
    unsigned r;
    asm("cvt.rna.tf32.f32 %0, %1;" : "=r"(r) : "f"(x));
    return r;
}

__device__ __forceinline__ void mma8(float c[4], const unsigned a[4],
                                     const unsigned b[2]) {
    asm volatile(
        "mma.sync.aligned.m16n8k8.row.col.f32.tf32.tf32.f32 "
        "{%0,%1,%2,%3}, {%4,%5,%6,%7}, {%8,%9}, {%0,%1,%2,%3};"
        : "+f"(c[0]), "+f"(c[1]), "+f"(c[2]), "+f"(c[3])
        : "r"(a[0]), "r"(a[1]), "r"(a[2]), "r"(a[3]), "r"(b[0]), "r"(b[1]));
}

__device__ __forceinline__ void mma16(float c[4], const unsigned a[4],
                                      const unsigned b[2]) {
    asm volatile(
        "mma.sync.aligned.m16n8k16.row.col.f32.bf16.bf16.f32 "
        "{%0,%1,%2,%3}, {%4,%5,%6,%7}, {%8,%9}, {%0,%1,%2,%3};"
        : "+f"(c[0]), "+f"(c[1]), "+f"(c[2]), "+f"(c[3])
        : "r"(a[0]), "r"(a[1]), "r"(a[2]), "r"(a[3]), "r"(b[0]), "r"(b[1]));
}

static __device__ __forceinline__ unsigned smem_u32(const void* p) {
    unsigned a;
    asm("{ .reg .u64 t; cvta.to.shared.u64 t, %1; cvt.u32.u64 %0, t; }"
        : "=r"(a) : "l"(p));
    return a;
}
__device__ __forceinline__ void cp16(unsigned dst, const void* src) {
    asm volatile("cp.async.cg.shared.global [%0], [%1], 16;"
                 :: "r"(dst), "l"(src) : "memory");
}
template <int N>
__device__ __forceinline__ void cpwait() {
    asm volatile("cp.async.wait_group %0;" :: "n"(N) : "memory");
}

// ------------------------------ prep kernels ------------------------------

__global__ void build_rnnin(const float* __restrict__ note) {
    int idx = blockIdx.x * blockDim.x + threadIdx.x;
    if (idx >= MM * K1) return;
    int f = idx & 63;
    int m = idx >> 6;
    int b = m / NN, n = m % NN;
    float v = 0.0f;
    if (f == 0) {
        v = (float)n * (1.0f / (float)NN);
    } else if (f < 13) {
        v = ((f - 1) == (n % 12)) ? 1.0f : 0.0f;
    } else if (f < 38) {
        int p = n + (f - 13) - 12;
        v = (p >= 0 && p < NN) ? note[b * NN + p] : 0.0f;
    } else if (f < 50) {
        const float* nb = note + b * NN + (f - 38) * 4;
        v = nb[0] + nb[1] + nb[2] + nb[3];
    }
    g_rnnin[idx] = v;
}

__global__ void pad_w0(const float* __restrict__ w) {  // (1024,50) -> (1024,64)
    int idx = blockIdx.x * blockDim.x + threadIdx.x;
    if (idx >= 1024 * K1) return;
    int k = idx & 63, r = idx >> 6;
    g_w0p[idx] = (k < 50) ? w[r * 50 + k] : 0.0f;
}

__global__ void prep_w2(const float* __restrict__ w) {  // n_Wih0 (512, 257)
    int idx = blockIdx.x * blockDim.x + threadIdx.x;
    if (idx >= 512 * 256) return;
    int k = idx & 255, r = idx >> 8;
    g_w2p[idx] = w[r * 257 + k];
    if (k == 0) g_wc[r] = w[r * 257 + 256];
}

// Interleave live gates: dst row c = 3u+g3, g3 in {i,g,o} = orig gates {0,2,3}
__global__ void prep_wi(const float* __restrict__ w, int K,
                        float* __restrict__ dst) {
    int idx = blockIdx.x * blockDim.x + threadIdx.x;
    if (idx >= 768 * K) return;
    int k = idx % K, c = idx / K;
    int u = c / 3, g3 = c - 3 * u;
    int ga = (g3 == 0) ? 0 : (g3 + 1);
    dst[idx] = w[(size_t)(ga * 256 + u) * K + k];
}

// scan weight (512 x 128) -> split-concat bf16 (512 x 384): [Wh|Wh|Wl]
__global__ void build_wsc(const float* __restrict__ w, bf16* __restrict__ dst) {
    int idx = blockIdx.x * blockDim.x + threadIdx.x;       // 512 * 128
    if (idx >= 512 * 128) return;
    int k = idx & 127, r = idx >> 7;
    float v = w[(size_t)r * 128 + k];
    bf16 hh = __float2bfloat16(v);
    bf16 hl = __float2bfloat16(v - __bfloat162float(hh));
    size_t o = (size_t)r * 384 + k;
    dst[o] = hh; dst[o + 128] = hh; dst[o + 256] = hl;
}

// ----------------------- tf32 tensor-core gate GEMM -----------------------
// (verbatim from the 2092us best)  out = X[M x K] @ W[C x K]^T, 3xTF32.
// Block tile 128 x NT, 8 warps (4m x 2n).  K chunks of 32 staged hi/lo.

template <int NT, int NI, bool ACT>
__global__ __launch_bounds__(256, 2)
void mma_gemm(const float* __restrict__ X, int K,
              const float* __restrict__ W,
              const float* __restrict__ bias,
              float* __restrict__ out, int ldo) {
    extern __shared__ float sh[];
    float* sAh = sh;
    float* sAl = sAh + 128 * 36;
    float* sBh = sAl + 128 * 36;
    float* sBl = sBh + NT * 36;

    const int t = threadIdx.x;
    const int lane = t & 31, wid = t >> 5;
    const int wm = wid & 3, wn = wid >> 2;
    const int gid = lane >> 2, tid4 = lane & 3;
    const int m0 = blockIdx.x * 128;
    const int c0 = blockIdx.y * NT;

    float acc[2][NI][4];
#pragma unroll
    for (int mi = 0; mi < 2; mi++)
#pragma unroll
        for (int ni = 0; ni < NI; ni++)
#pragma unroll
            for (int q = 0; q < 4; q++) acc[mi][ni][q] = 0.0f;

    const int nchunks = K >> 5;
    for (int kc = 0; kc < nchunks; kc++) {
        __syncthreads();
#pragma unroll
        for (int j = 0; j < 4; j++) {
            int i = t + 256 * j;
            int r = i >> 3, c4 = (i & 7) * 4;
            float4 v = *(const float4*)&X[(size_t)(m0 + r) * K + kc * 32 + c4];
            float4 h, l;
            h.x = __uint_as_float(tf32r(v.x)); l.x = __uint_as_float(tf32r(v.x - h.x));
            h.y = __uint_as_float(tf32r(v.y)); l.y = __uint_as_float(tf32r(v.y - h.y));
            h.z = __uint_as_float(tf32r(v.z)); l.z = __uint_as_float(tf32r(v.z - h.z));
            h.w = __uint_as_float(tf32r(v.w)); l.w = __uint_as_float(tf32r(v.w - h.w));
            *(float4*)&sAh[r * 36 + c4] = h;
            *(float4*)&sAl[r * 36 + c4] = l;
        }
#pragma unroll
        for (int j = 0; j < NT / 32; j++) {
            int i = t + 256 * j;
            int r = i >> 3, c4 = (i & 7) * 4;
            float4 v = *(const float4*)&W[(size_t)(c0 + r) * K + kc * 32 + c4];
            float4 h, l;
            h.x = __uint_as_float(tf32r(v.x)); l.x = __uint_as_float(tf32r(v.x - h.x));
            h.y = __uint_as_float(tf32r(v.y)); l.y = __uint_as_float(tf32r(v.y - h.y));
            h.z = __uint_as_float(tf32r(v.z)); l.z = __uint_as_float(tf32r(v.z - h.z));
            h.w = __uint_as_float(tf32r(v.w)); l.w = __uint_as_float(tf32r(v.w - h.w));
            *(float4*)&sBh[r * 36 + c4] = h;
            *(float4*)&sBl[r * 36 + c4] = l;
        }
        __syncthreads();

#pragma unroll
        for (int kk = 0; kk < 4; kk++) {
            const int kb = kk * 8;
            unsigned Ah[2][4], Al[2][4], Bh[NI][2], Bl[NI][2];
#pragma unroll
            for (int mi = 0; mi < 2; mi++) {
                int r = wm * 32 + mi * 16 + gid;
                Ah[mi][0] = __float_as_uint(sAh[r * 36 + kb + tid4]);
                Ah[mi][1] = __float_as_uint(sAh[(r + 8) * 36 + kb + tid4]);
                Ah[mi][2] = __float_as_uint(sAh[r * 36 + kb + tid4 + 4]);
                Ah[mi][3] = __float_as_uint(sAh[(r + 8) * 36 + kb + tid4 + 4]);
                Al[mi][0] = __float_as_uint(sAl[r * 36 + kb + tid4]);
                Al[mi][1] = __float_as_uint(sAl[(r + 8) * 36 + kb + tid4]);
                Al[mi][2] = __float_as_uint(sAl[r * 36 + kb + tid4 + 4]);
                Al[mi][3] = __float_as_uint(sAl[(r + 8) * 36 + kb + tid4 + 4]);
            }
#pragma unroll
            for (int ni = 0; ni < NI; ni++) {
                int c = wn * (NT / 2) + ni * 8 + gid;
                Bh[ni][0] = __float_as_uint(sBh[c * 36 + kb + tid4]);
                Bh[ni][1] = __float_as_uint(sBh[c * 36 + kb + tid4 + 4]);
                Bl[ni][0] = __float_as_uint(sBl[c * 36 + kb + tid4]);
                Bl[ni][1] = __float_as_uint(sBl[c * 36 + kb + tid4 + 4]);
            }
#pragma unroll
            for (int mi = 0; mi < 2; mi++)
#pragma unroll
                for (int ni = 0; ni < NI; ni++) {
                    mma8(acc[mi][ni], Ah[mi], Bh[ni]);
                    mma8(acc[mi][ni], Al[mi], Bh[ni]);
                    mma8(acc[mi][ni], Ah[mi], Bl[ni]);
                }
        }
    }

    __syncthreads();
    const int NTS = NT + 4;
#pragma unroll
    for (int mi = 0; mi < 2; mi++)
#pragma unroll
        for (int ni = 0; ni < NI; ni++) {
            int r = wm * 32 + mi * 16 + gid;
            int c = wn * (NT / 2) + ni * 8 + tid4 * 2;
            sh[r * NTS + c]           = acc[mi][ni][0];
            sh[r * NTS + c + 1]       = acc[mi][ni][1];
            sh[(r + 8) * NTS + c]     = acc[mi][ni][2];
            sh[(r + 8) * NTS + c + 1] = acc[mi][ni][3];
        }
    __syncthreads();

    if constexpr (ACT) {
        const int ul = t & 31, mr = t >> 5;
        const int ug = blockIdx.y * 32 + ul;
        const float bi = bias[ug];
        const float bg = bias[2 * 256 + ug];
        const float bo = bias[3 * 256 + ug];
#pragma unroll
        for (int j = 0; j < 16; j++) {
            int m = mr + j * 8;
            float gi = sh[m * NTS + ul * 3 + 0] + bi;
            float gg = sh[m * NTS + ul * 3 + 1] + bg;
            float go = sh[m * NTS + ul * 3 + 2] + bo;
            float cc = sigf(gi) * tanhf(gg);
            out[(size_t)(m0 + m) * ldo + ug] = sigf(go) * tanhf(cc);
        }
    } else {
        const int cl = t & 63, mr = t >> 6;
#pragma unroll
        for (int j = 0; j < 32; j++) {
            int m = mr + j * 4;
            out[(size_t)(m0 + m) * ldo + c0 + cl] = sh[m * NTS + cl];
        }
    }
}

// ------------------- tensorized note-axis scan (cp.async) ------------------
// 64 blocks x 16 batches, 256 threads (8 warps).  Recurrent GEMMs
// M16 x N512 x K'384 bf16 (3x split).  Weights stream through a 4-stage
// cp.async ring (3 groups in flight => L2 latency hidden).
// smem: sWst 163840 | sH1 12544 | sH2 12544 | sG 33280 | sWo 512 = 222720 B

__device__ __forceinline__ void issue_chunk(const bf16* __restrict__ W, int c,
                                            unsigned stage_u32, int t) {
    const int r0 = t >> 2, p = t & 3;
#pragma unroll
    for (int j = 0; j < 8; j++) {
        int row = r0 + 64 * j;
        cp16(stage_u32 + row * 80 + p * 16,
             W + (size_t)row * 384 + c * 32 + p * 8);
    }
    asm volatile("cp.async.commit_group;" ::: "memory");
}

__device__ __forceinline__ void scan_pass_async(float acc[8][4],
                                                const bf16* __restrict__ W,
                                                const bf16* sH,
                                                const bf16* sWst,
                                                unsigned sWst_u32,
                                                int wid, int gid, int tid4, int t) {
    issue_chunk(W, 0, sWst_u32, t);
    issue_chunk(W, 1, sWst_u32 + 40960, t);
    issue_chunk(W, 2, sWst_u32 + 81920, t);
    for (int c = 0; c < 12; c++) {
        if (c + 3 < 12) issue_chunk(W, c + 3, sWst_u32 + ((c + 3) & 3) * 40960, t);
        if (c <= 8)      cpwait<3>();
        else if (c == 9) cpwait<2>();
        else if (c == 10) cpwait<1>();
        else             cpwait<0>();
        __syncthreads();
        const bf16* cur = sWst + (c & 3) * 20480;
#pragma unroll
        for (int kh = 0; kh < 2; kh++) {
            const bf16* hrow = sH + gid * 392 + c * 32 + kh * 16 + tid4 * 2;
            unsigned Af[4];
            Af[0] = *(const unsigned*)hrow;
            Af[1] = *(const unsigned*)(hrow + 8 * 392);
            Af[2] = *(const unsigned*)(hrow + 8);
            Af[3] = *(const unsigned*)(hrow + 8 * 392 + 8);
#pragma unroll
            for (int ni = 0; ni < 8; ni++) {
                const bf16* wrow = cur + (wid * 64 + ni * 8 + gid) * 40
                                       + kh * 16 + tid4 * 2;
                unsigned Bf[2];
                Bf[0] = *(const unsigned*)wrow;
                Bf[1] = *(const unsigned*)(wrow + 8);
                mma16(acc[ni], Af, Bf);
            }
        }
        __syncthreads();
    }
}

__device__ __forceinline__ void acc_to_sG(const float acc[8][4], float* sG,
                                          int wid, int gid, int tid4) {
#pragma unroll
    for (int ni = 0; ni < 8; ni++) {
        int c = wid * 64 + ni * 8 + tid4 * 2;
        sG[gid * 520 + c]           = acc[ni][0];
        sG[gid * 520 + c + 1]       = acc[ni][1];
        sG[(gid + 8) * 520 + c]     = acc[ni][2];
        sG[(gid + 8) * 520 + c + 1] = acc[ni][3];
    }
}

__global__ __launch_bounds__(256, 1)
void scan_kernel(const float* __restrict__ targets,
                 const float* __restrict__ nb0,
                 const float* __restrict__ nb1,
                 const float* __restrict__ outW,
                 const float* __restrict__ outb,
                 float* __restrict__ out) {
    extern __shared__ char sm[];
    bf16*  sWst = (bf16*)sm;                   // 4 x 512 x 40
    bf16*  sH1  = (bf16*)(sm + 163840);        // 16 x 392
    bf16*  sH2  = (bf16*)(sm + 176384);        // 16 x 392
    float* sG   = (float*)(sm + 188928);       // 16 x 520
    float* sWo  = (float*)(sm + 222208);       // 128
    const unsigned sWst_u32 = smem_u32(sWst);

    const int t = threadIdx.x;
    const int lane = t & 31, wid = t >> 5;
    const int gid = lane >> 2, tid4 = lane & 3;
    const int u = t & 127, bp = t >> 7;        // pointwise mapping
    const int B0 = blockIdx.x * 16;

    if (t < 128) sWo[t] = outW[t];
    for (int i = t; i < 6272; i += 256) ((unsigned*)sH1)[i] = 0u;  // sH1+sH2

    float c1[8], c2[8];
#pragma unroll
    for (int j = 0; j < 8; j++) { c1[j] = 0.0f; c2[j] = 0.0f; }
    float b0r[4], b1r[4], wcr[4];
#pragma unroll
    for (int g = 0; g < 4; g++) {
        b0r[g] = nb0[g * 128 + u];
        b1r[g] = nb1[g * 128 + u];
        wcr[g] = g_wc[g * 128 + u];
    }
    const float ob = outb[0];
    __syncthreads();

    const bf16* Wh0 = g_wcat;
    const bf16* Wi1 = g_wcat + 512 * 384;
    const bf16* Wh1 = g_wcat + 2 * 512 * 384;

    for (int n = 0; n < NN; n++) {
        // ---- layer 0: gates = h1_prev @ Whh0^T ----
        float acc[8][4];
#pragma unroll
        for (int ni = 0; ni < 8; ni++)
#pragma unroll
            for (int q = 0; q < 4; q++) acc[ni][q] = 0.0f;
        scan_pass_async(acc, Wh0, sH1, sWst, sWst_u32, wid, gid, tid4, t);
        acc_to_sG(acc, sG, wid, gid, tid4);
        __syncthreads();

        // pointwise L0 (thread = unit u, batches bp*8..bp*8+7)
#pragma unroll
        for (int j = 0; j < 8; j++) {
            int b = bp * 8 + j, bg = B0 + b;
            float cond = (n == 0) ? 0.0f : targets[bg * NN + n - 1];
            size_t m = (size_t)bg * NN + n;
            float gi = sG[b * 520 + u]       + g_xw[m * 512 + u]       + b0r[0] + cond * wcr[0];
            float gf = sG[b * 520 + 128 + u] + g_xw[m * 512 + 128 + u] + b0r[1] + cond * wcr[1];
            float gg = sG[b * 520 + 256 + u] + g_xw[m * 512 + 256 + u] + b0r[2] + cond * wcr[2];
            float go = sG[b * 520 + 384 + u] + g_xw[m * 512 + 384 + u] + b0r[3] + cond * wcr[3];
            float cc = sigf(gf) * c1[j] + sigf(gi) * tanhf(gg);
            c1[j] = cc;
            float h = sigf(go) * tanhf(cc);
            bf16 hh = __float2bfloat16(h);
            bf16 hl = __float2bfloat16(h - __bfloat162float(hh));
            sH1[b * 392 + u] = hh;
            sH1[b * 392 + 128 + u] = hl;
            sH1[b * 392 + 256 + u] = hh;
        }
        __syncthreads();

        // ---- layer 1: gates = h1 @ Wih1^T + h2_prev @ Whh1^T ----
#pragma unroll
        for (int ni = 0; ni < 8; ni++)
#pragma unroll
            for (int q = 0; q < 4; q++) acc[ni][q] = 0.0f;
        scan_pass_async(acc, Wi1, sH1, sWst, sWst_u32, wid, gid, tid4, t);
        scan_pass_async(acc, Wh1, sH2, sWst, sWst_u32, wid, gid, tid4, t);
        acc_to_sG(acc, sG, wid, gid, tid4);
        __syncthreads();

        // pointwise L1; h2 (fp32) parked in sG[b][u]
#pragma unroll
        for (int j = 0; j < 8; j++) {
            int b = bp * 8 + j;
            float gi = sG[b * 520 + u]       + b1r[0];
            float gf = sG[b * 520 + 128 + u] + b1r[1];
            float gg = sG[b * 520 + 256 + u] + b1r[2];
            float go = sG[b * 520 + 384 + u] + b1r[3];
            float cc = sigf(gf) * c2[j] + sigf(gi) * tanhf(gg);
            c2[j] = cc;
            float h = sigf(go) * tanhf(cc);
            bf16 hh = __float2bfloat16(h);
            bf16 hl = __float2bfloat16(h - __bfloat162float(hh));
            sH2[b * 392 + u] = hh;
            sH2[b * 392 + 128 + u] = hl;
            sH2[b * 392 + 256 + u] = hh;
            sG[b * 520 + u] = h;           // own (b,u) slot: no race
        }
        __syncthreads();

        // ---- output: warp wid -> batches 2*wid, 2*wid+1 (half-warps) ----
        {
            int b2 = 2 * wid + (lane >> 4), ul = lane & 15;
            float p = 0.0f;
#pragma unroll
            for (int j = 0; j < 8; j++)
                p += sG[b2 * 520 + ul + 16 * j] * sWo[ul + 16 * j];
#pragma unroll
            for (int off = 8; off; off >>= 1)
                p += __shfl_down_sync(0xffffffffu, p, off, 16);
            if (ul == 0) out[(B0 + b2) * NN + n] = sigf(p + ob);
        }
        // next layer-0 pass re-syncs before sG is overwritten
    }
}

// --------------------------------- launch ---------------------------------

extern "C" void kernel_launch(void* const* d_in, const int* in_sizes, int n_in,
                              void* d_out, int out_size) {
    (void)in_sizes; (void)n_in; (void)out_size;
    const float* note    = (const float*)d_in[0];
    const float* targets = (const float*)d_in[1];
    const float* tWih0   = (const float*)d_in[2];
    const float* tb0     = (const float*)d_in[4];
    const float* tWih1   = (const float*)d_in[5];
    const float* tb1     = (const float*)d_in[7];
    const float* nWih0   = (const float*)d_in[8];
    const float* nWhh0   = (const float*)d_in[9];
    const float* nb0     = (const float*)d_in[10];
    const float* nWih1   = (const float*)d_in[11];
    const float* nWhh1   = (const float*)d_in[12];
    const float* nb1     = (const float*)d_in[13];
    const float* outW    = (const float*)d_in[14];
    const float* outb    = (const float*)d_in[15];
    float* out = (float*)d_out;

    float *p_rnnin, *p_w0p, *p_w0i, *p_w1i, *p_h1, *p_feats, *p_w2p, *p_xw;
    bf16 *p_wcat;
    cudaGetSymbolAddress((void**)&p_rnnin, g_rnnin);
    cudaGetSymbolAddress((void**)&p_w0p,   g_w0p);
    cudaGetSymbolAddress((void**)&p_w0i,   g_w0i);
    cudaGetSymbolAddress((void**)&p_w1i,   g_w1i);
    cudaGetSymbolAddress((void**)&p_h1,    g_h1);
    cudaGetSymbolAddress((void**)&p_feats, g_feats);
    cudaGetSymbolAddress((void**)&p_w2p,   g_w2p);
    cudaGetSymbolAddress((void**)&p_xw,    g_xw);
    cudaGetSymbolAddress((void**)&p_wcat,  g_wcat);

    build_rnnin<<<(MM * K1) / 256, 256>>>(note);
    pad_w0<<<(1024 * K1) / 256, 256>>>(tWih0);
    prep_w2<<<(512 * 256) / 256, 256>>>(nWih0);
    prep_wi<<<(768 * K1 + 255) / 256, 256>>>(p_w0p, K1, p_w0i);
    prep_wi<<<(768 * 256 + 255) / 256, 256>>>(tWih1, 256, p_w1i);
    build_wsc<<<(512 * 128) / 256, 256>>>(nWhh0, p_wcat);
    build_wsc<<<(512 * 128) / 256, 256>>>(nWih1, p_wcat + 512 * 384);
    build_wsc<<<(512 * 128) / 256, 256>>>(nWhh1, p_wcat + 2 * 512 * 384);

    const int smemA = (128 * 36 * 2 + 96 * 36 * 2) * (int)sizeof(float); // 64512
    const int smemB = (128 * 36 * 2 + 64 * 36 * 2) * (int)sizeof(float); // 55296
    cudaFuncSetAttribute((const void*)mma_gemm<96, 6, true>,
                         cudaFuncAttributeMaxDynamicSharedMemorySize, smemA);
    cudaFuncSetAttribute((const void*)mma_gemm<64, 4, false>,
                         cudaFuncAttributeMaxDynamicSharedMemorySize, smemB);

    // h1 = act(rnn_in @ t_Wih0.T + b0)        (K padded to 64)
    mma_gemm<96, 6, true><<<dim3(384, 8), 256, smemA>>>(p_rnnin, K1, p_w0i,
                                                        tb0, p_h1, 256);
    // feats = act(h1 @ t_Wih1.T + b1)
    mma_gemm<96, 6, true><<<dim3(384, 8), 256, smemA>>>(p_h1, 256, p_w1i,
                                                        tb1, p_feats, 256);
    // g_xw = feats @ n_Wih0[:, :256].T        (raw gates for the scan)
    mma_gemm<64, 4, false><<<dim3(384, 8), 256, smemB>>>(p_feats, 256, p_w2p,
                                                         nullptr, p_xw, 512);

    const int smemS = 222720;
    cudaFuncSetAttribute(scan_kernel, cudaFuncAttributeMaxDynamicSharedMemorySize, smemS);
    scan_kernel<<<64, 256, smemS>>>(targets, nb0, nb1, outW, outb, out);
}

// round 12
// speedup vs baseline: 1.2011x; 1.1787x over previous
#include <cuda_runtime.h>
#include <cuda_bf16.h>
#include <math.h>

// ---------------------------------------------------------------------------
// DeepJ biaxial LSTM.  B=1024, N=48, TU=256, NU=128, IN_T=50 (pad 64).
//   - time-axis layers: single step h=c=0 => feed-forward gate GEMMs on
//     mma.sync m16n8k16 bf16 with 3xK hi/lo split (A'=[Ah|Al|Ah],
//     W'=[Wh|Wh|Wl]) and FUSED activation epilogue that directly emits the
//     next layer's split-concat bf16 input (no raw-gate round trips).
//   - N-major block raster so consecutive blocks reuse the A tile via L2.
//   - note-axis scan: persistent scalar fp32 (verbatim from the 2092us best).
// ---------------------------------------------------------------------------

#define BB 1024
#define NN 48
#define MM (BB * NN)   // 49152

typedef __nv_bfloat16 bf16;

// scratch (device globals: allocation-free)
__device__ bf16  g_ac0[MM * 192];      // rnn_in split-concat (K'=192)
__device__ bf16  g_ac1[MM * 768];      // h1 split-concat     (K'=768)
__device__ bf16  g_ac2[MM * 768];      // feats split-concat  (K'=768)
__device__ bf16  g_w0i[768 * 192];     // t_Wih0 live-gate interleaved split-concat
__device__ bf16  g_w1i[768 * 768];     // t_Wih1 live-gate interleaved split-concat
__device__ bf16  g_w2c[512 * 768];     // n_Wih0[:, :256] split-concat (gate-blocked)
__device__ float g_wc[512];            // n_Wih0[:, 256] (cond column)
__device__ float g_xw[MM * 512];       // raw gates for the scan

__device__ __forceinline__ float sigf(float x) { return 1.0f / (1.0f + expf(-x)); }

__device__ __forceinline__ void mma16(float c[4], const unsigned a[4],
                                      const unsigned b[2]) {
    asm volatile(
        "mma.sync.aligned.m16n8k16.row.col.f32.bf16.bf16.f32 "
        "{%0,%1,%2,%3}, {%4,%5,%6,%7}, {%8,%9}, {%0,%1,%2,%3};"
        : "+f"(c[0]), "+f"(c[1]), "+f"(c[2]), "+f"(c[3])
        : "r"(a[0]), "r"(a[1]), "r"(a[2]), "r"(a[3]), "r"(b[0]), "r"(b[1]));
}

// ----------------------------- prep kernels -------------------------------

__device__ __forceinline__ void split3(float v, bf16* p0, bf16* p1, bf16* p2) {
    bf16 hh = __float2bfloat16(v);
    bf16 hl = __float2bfloat16(v - __bfloat162float(hh));
    *p0 = hh; *p1 = hl; *p2 = hh;          // activations: [hi | lo | hi]
}
__device__ __forceinline__ void splitw(float v, bf16* p0, bf16* p1, bf16* p2) {
    bf16 hh = __float2bfloat16(v);
    bf16 hl = __float2bfloat16(v - __bfloat162float(hh));
    *p0 = hh; *p1 = hh; *p2 = hl;          // weights: [hi | hi | lo]
}

__global__ void build_ac0(const float* __restrict__ note) {
    int idx = blockIdx.x * blockDim.x + threadIdx.x;   // MM * 64
    if (idx >= MM * 64) return;
    int f = idx & 63;
    int m = idx >> 6;
    int b = m / NN, n = m % NN;
    float v = 0.0f;
    if (f == 0) {
        v = (float)n * (1.0f / (float)NN);
    } else if (f < 13) {
        v = ((f - 1) == (n % 12)) ? 1.0f : 0.0f;
    } else if (f < 38) {
        int p = n + (f - 13) - 12;
        v = (p >= 0 && p < NN) ? note[b * NN + p] : 0.0f;
    } else if (f < 50) {
        const float* nb = note + b * NN + (f - 38) * 4;
        v = nb[0] + nb[1] + nb[2] + nb[3];
    }
    size_t o = (size_t)m * 192 + f;
    split3(v, &g_ac0[o], &g_ac0[o + 64], &g_ac0[o + 128]);
}

// t_Wih0 (1024 x 50) -> interleaved live gates (row 3u+g3), K pad 64, split x3
__global__ void build_w0i(const float* __restrict__ w) {
    int idx = blockIdx.x * blockDim.x + threadIdx.x;   // 768 * 64
    if (idx >= 768 * 64) return;
    int k = idx & 63, r = idx >> 6;
    int u = r / 3, g3 = r - 3 * u;
    int ga = (g3 == 0) ? 0 : g3 + 1;
    float v = (k < 50) ? w[(size_t)(ga * 256 + u) * 50 + k] : 0.0f;
    size_t o = (size_t)r * 192 + k;
    splitw(v, &g_w0i[o], &g_w0i[o + 64], &g_w0i[o + 128]);
}

// t_Wih1 (1024 x 256) -> interleaved live gates, K'=768
__global__ void build_w1i(const float* __restrict__ w) {
    int idx = blockIdx.x * blockDim.x + threadIdx.x;   // 768 * 256
    if (idx >= 768 * 256) return;
    int k = idx & 255, r = idx >> 8;
    int u = r / 3, g3 = r - 3 * u;
    int ga = (g3 == 0) ? 0 : g3 + 1;
    float v = w[(size_t)(ga * 256 + u) * 256 + k];
    size_t o = (size_t)r * 768 + k;
    splitw(v, &g_w1i[o], &g_w1i[o + 256], &g_w1i[o + 512]);
}

// n_Wih0 (512 x 257) gate-blocked -> split-concat K'=768 ; extracts cond col
__global__ void build_w2c(const float* __restrict__ w) {
    int idx = blockIdx.x * blockDim.x + threadIdx.x;   // 512 * 256
    if (idx >= 512 * 256) return;
    int k = idx & 255, r = idx >> 8;
    float v = w[(size_t)r * 257 + k];
    size_t o = (size_t)r * 768 + k;
    splitw(v, &g_w2c[o], &g_w2c[o + 256], &g_w2c[o + 512]);
    if (k == 0) g_wc[r] = w[(size_t)r * 257 + 256];
}

// ------------------ bf16 mma.sync gate GEMM, fused activation --------------
// C = A'[M x K'] @ W'[NT_total x K']^T.  Block tile 128 x NT, 8 warps
// (4m x 2n), K chunks of 32.  Staging [row][k] stride 40 bf16.
// blockIdx.x = n-tile (so consecutive blocks share the A tile via L2),
// blockIdx.y = m-tile.
// ACT=true : NT=96 = 32 units x (i,g,o) interleaved; epilogue computes h and
//            emits split-concat bf16 rows (width 768) for the next GEMM.
// ACT=false: NT=128 raw gate columns -> fp32 out (ldo=512).

template <int NT, int NI, bool ACT>
__global__ __launch_bounds__(256)
void gemm_bfa(const bf16* __restrict__ A, int Kp,
              const bf16* __restrict__ W,
              const float* __restrict__ bias,
              bf16* __restrict__ outb_, float* __restrict__ outf) {
    extern __shared__ char smem[];
    bf16* sA = (bf16*)smem;                       // [128][40]
    bf16* sB = (bf16*)(smem + 128 * 40 * 2);      // [NT][40]

    const int t = threadIdx.x;
    const int lane = t & 31, wid = t >> 5;
    const int wm = wid & 3, wn = wid >> 2;
    const int gid = lane >> 2, tid4 = lane & 3;
    const int m0 = blockIdx.y * 128;
    const int c0 = blockIdx.x * NT;

    float acc[2][NI][4];
#pragma unroll
    for (int mi = 0; mi < 2; mi++)
#pragma unroll
        for (int ni = 0; ni < NI; ni++)
#pragma unroll
            for (int q = 0; q < 4; q++) acc[mi][ni][q] = 0.0f;

    // loaders: rows x 4 uint4 per 32-k chunk
    const int ar = t >> 2, ap = (t & 3) * 8;      // A slots: ar, ar+64
    int  br[2]; bool bval[2];
#pragma unroll
    for (int j = 0; j < 2; j++) {
        int lin = t + 256 * j;
        bval[j] = (lin < NT * 4);
        br[j] = bval[j] ? lin : 0;
    }

    uint4 pa0, pa1, pb[2];
    pa0 = *(const uint4*)(A + (size_t)(m0 + ar) * Kp + ap);
    pa1 = *(const uint4*)(A + (size_t)(m0 + ar + 64) * Kp + ap);
#pragma unroll
    for (int j = 0; j < 2; j++)
        if (bval[j])
            pb[j] = *(const uint4*)(W + (size_t)(c0 + (br[j] >> 2)) * Kp
                                      + (br[j] & 3) * 8);

    const int nchunks = Kp >> 5;
    for (int kc = 0; kc < nchunks; kc++) {
        *(uint4*)&sA[ar * 40 + ap]        = pa0;
        *(uint4*)&sA[(ar + 64) * 40 + ap] = pa1;
#pragma unroll
        for (int j = 0; j < 2; j++)
            if (bval[j])
                *(uint4*)&sB[(br[j] >> 2) * 40 + (br[j] & 3) * 8] = pb[j];
        __syncthreads();

        if (kc + 1 < nchunks) {
            int ko = (kc + 1) * 32;
            pa0 = *(const uint4*)(A + (size_t)(m0 + ar) * Kp + ko + ap);
            pa1 = *(const uint4*)(A + (size_t)(m0 + ar + 64) * Kp + ko + ap);
#pragma unroll
            for (int j = 0; j < 2; j++)
                if (bval[j])
                    pb[j] = *(const uint4*)(W + (size_t)(c0 + (br[j] >> 2)) * Kp
                                              + ko + (br[j] & 3) * 8);
        }

#pragma unroll
        for (int kh = 0; kh < 2; kh++) {
            const int kb = kh * 16;
            unsigned Af[2][4], Bf[NI][2];
#pragma unroll
            for (int mi = 0; mi < 2; mi++) {
                int r = wm * 32 + mi * 16 + gid;
                Af[mi][0] = *(const unsigned*)&sA[r * 40 + kb + tid4 * 2];
                Af[mi][1] = *(const unsigned*)&sA[(r + 8) * 40 + kb + tid4 * 2];
                Af[mi][2] = *(const unsigned*)&sA[r * 40 + kb + tid4 * 2 + 8];
                Af[mi][3] = *(const unsigned*)&sA[(r + 8) * 40 + kb + tid4 * 2 + 8];
            }
#pragma unroll
            for (int ni = 0; ni < NI; ni++) {
                int c = wn * (NT / 2) + ni * 8 + gid;
                Bf[ni][0] = *(const unsigned*)&sB[c * 40 + kb + tid4 * 2];
                Bf[ni][1] = *(const unsigned*)&sB[c * 40 + kb + tid4 * 2 + 8];
            }
#pragma unroll
            for (int mi = 0; mi < 2; mi++)
#pragma unroll
                for (int ni = 0; ni < NI; ni++)
                    mma16(acc[mi][ni], Af[mi], Bf[ni]);
        }
        __syncthreads();
    }

    // dump accumulators to smem [128][NT+4]
    float* sd = (float*)smem;
    const int NTS = NT + 4;
#pragma unroll
    for (int mi = 0; mi < 2; mi++)
#pragma unroll
        for (int ni = 0; ni < NI; ni++) {
            int r = wm * 32 + mi * 16 + gid;
            int c = wn * (NT / 2) + ni * 8 + tid4 * 2;
            sd[r * NTS + c]           = acc[mi][ni][0];
            sd[r * NTS + c + 1]       = acc[mi][ni][1];
            sd[(r + 8) * NTS + c]     = acc[mi][ni][2];
            sd[(r + 8) * NTS + c + 1] = acc[mi][ni][3];
        }
    __syncthreads();

    if constexpr (ACT) {
        const int ul = t & 31, mr = t >> 5;
        const int ug = blockIdx.x * 32 + ul;        // global unit
        const float bi = bias[ug];
        const float bg = bias[2 * 256 + ug];
        const float bo = bias[3 * 256 + ug];
#pragma unroll
        for (int j = 0; j < 16; j++) {
            int m = mr + j * 8;
            float gi = sd[m * NTS + ul * 3 + 0] + bi;
            float gg = sd[m * NTS + ul * 3 + 1] + bg;
            float go = sd[m * NTS + ul * 3 + 2] + bo;
            float h = sigf(go) * tanhf(sigf(gi) * tanhf(gg));
            size_t o = (size_t)(m0 + m) * 768 + ug;
            split3(h, &outb_[o], &outb_[o + 256], &outb_[o + 512]);
        }
    } else {
#pragma unroll
        for (int j = 0; j < 16; j++) {
            int i = j * 256 + t;                    // 128 x 32 float4
            int r = i >> 5, c4 = i & 31;
            *(float4*)&outf[(size_t)(m0 + r) * 512 + c0 + c4 * 4] =
                *(float4*)&sd[r * NTS + c4 * 4];
        }
    }
}

// ------------------------------ note-axis scan -----------------------------
// (verbatim from the 2092us best)  128 blocks x 8 batches, 256 threads.

__device__ __forceinline__ void load_wtile_regs(float4 pre[8],
                                                const float* __restrict__ W,
                                                int kt, int t) {
#pragma unroll
    for (int i = 0; i < 8; i++) {
        int lin = t + 256 * i;
        int r = lin >> 2, k4 = lin & 3;
        pre[i] = *(const float4*)&W[r * 128 + kt + k4 * 4];
    }
}

__device__ __forceinline__ void sts_wtile(float* dst, const float4 pre[8], int t) {
#pragma unroll
    for (int i = 0; i < 8; i++) {
        int lin = t + 256 * i;
        int r = lin >> 2, k4 = lin & 3;
        *(float4*)&dst[r * 20 + k4 * 4] = pre[i];
    }
}

__device__ __forceinline__ void accum_tile(float acc[4][4], const float* sWt,
                                           const float* sH, int kt, int u, int bp) {
#pragma unroll
    for (int kk = 0; kk < 16; kk += 4) {
        float4 wv[4];
#pragma unroll
        for (int g = 0; g < 4; g++)
            wv[g] = *(const float4*)&sWt[(g * 128 + u) * 20 + kk];
#pragma unroll
        for (int b = 0; b < 4; b++) {
            float4 hv = *(const float4*)&sH[(bp * 4 + b) * 128 + kt + kk];
#pragma unroll
            for (int g = 0; g < 4; g++) {
                acc[b][g] += hv.x * wv[g].x;
                acc[b][g] += hv.y * wv[g].y;
                acc[b][g] += hv.z * wv[g].z;
                acc[b][g] += hv.w * wv[g].w;
            }
        }
    }
}

__device__ __forceinline__ void gemm_pass(float acc[4][4],
                                          const float* __restrict__ W,
                                          const float* sH, float* sW,
                                          int t, int u, int bp) {
    float4 pre[8];
    load_wtile_regs(pre, W, 0, t);
    sts_wtile(sW, pre, t);
    __syncthreads();
    for (int it = 0; it < 8; it++) {
        float* cur = sW + (it & 1) * 10240;
        if (it < 7) load_wtile_regs(pre, W, (it + 1) * 16, t);
        accum_tile(acc, cur, sH, it * 16, u, bp);
        if (it < 7) sts_wtile(sW + ((it + 1) & 1) * 10240, pre, t);
        __syncthreads();
    }
}

__global__ __launch_bounds__(256, 1)
void scan_kernel(const float* __restrict__ targets,
                 const float* __restrict__ Whh0,
                 const float* __restrict__ nb0,
                 const float* __restrict__ Wih1,
                 const float* __restrict__ Whh1,
                 const float* __restrict__ nb1,
                 const float* __restrict__ outW,
                 const float* __restrict__ outb,
                 float* __restrict__ out) {
    extern __shared__ float sh[];
    float* sW  = sh;              // 2 x 512 x 20 = 20480
    float* sH1 = sh + 20480;      // 8 x 128
    float* sH2 = sH1 + 1024;      // 8 x 128
    float* sWo = sH2 + 1024;      // 128

    const int t = threadIdx.x;
    const int u = t & 127, bp = t >> 7;
    const int B0 = blockIdx.x * 8;

    if (t < 128) sWo[t] = outW[t];
    for (int i = t; i < 2048; i += 256) sH1[i] = 0.0f;

    float c1[4] = {0, 0, 0, 0}, c2[4] = {0, 0, 0, 0};
    float b0r[4], b1r[4], wcr[4];
#pragma unroll
    for (int g = 0; g < 4; g++) {
        b0r[g] = nb0[g * 128 + u];
        b1r[g] = nb1[g * 128 + u];
        wcr[g] = g_wc[g * 128 + u];
    }
    const float ob = outb[0];
    __syncthreads();

    for (int n = 0; n < NN; n++) {
        float acc[4][4];
#pragma unroll
        for (int b = 0; b < 4; b++) {
            int bg = B0 + bp * 4 + b;
            float cond = (n == 0) ? 0.0f : targets[bg * NN + n - 1];
            size_t m = (size_t)bg * NN + n;
#pragma unroll
            for (int g = 0; g < 4; g++)
                acc[b][g] = g_xw[m * 512 + g * 128 + u] + b0r[g] + cond * wcr[g];
        }
        gemm_pass(acc, Whh0, sH1, sW, t, u, bp);

        float h1n[4];
#pragma unroll
        for (int b = 0; b < 4; b++) {
            float cc = sigf(acc[b][1]) * c1[b] + sigf(acc[b][0]) * tanhf(acc[b][2]);
            c1[b] = cc;
            h1n[b] = sigf(acc[b][3]) * tanhf(cc);
        }
#pragma unroll
        for (int b = 0; b < 4; b++) sH1[(bp * 4 + b) * 128 + u] = h1n[b];
        __syncthreads();

        float acc2[4][4];
#pragma unroll
        for (int b = 0; b < 4; b++)
#pragma unroll
            for (int g = 0; g < 4; g++) acc2[b][g] = b1r[g];
        gemm_pass(acc2, Wih1, sH1, sW, t, u, bp);
        gemm_pass(acc2, Whh1, sH2, sW, t, u, bp);

        float h2n[4];
#pragma unroll
        for (int b = 0; b < 4; b++) {
            float cc = sigf(acc2[b][1]) * c2[b] + sigf(acc2[b][0]) * tanhf(acc2[b][2]);
            c2[b] = cc;
            h2n[b] = sigf(acc2[b][3]) * tanhf(cc);
        }
#pragma unroll
        for (int b = 0; b < 4; b++) sH2[(bp * 4 + b) * 128 + u] = h2n[b];
        __syncthreads();

        int w = t >> 5, lane = t & 31;
        float p = 0.0f;
#pragma unroll
        for (int j = 0; j < 4; j++)
            p += sH2[w * 128 + lane + 32 * j] * sWo[lane + 32 * j];
#pragma unroll
        for (int off = 16; off; off >>= 1)
            p += __shfl_down_sync(0xffffffffu, p, off);
        if (lane == 0) out[(B0 + w) * NN + n] = sigf(p + ob);
    }
}

// --------------------------------- launch ---------------------------------

extern "C" void kernel_launch(void* const* d_in, const int* in_sizes, int n_in,
                              void* d_out, int out_size) {
    (void)in_sizes; (void)n_in; (void)out_size;
    const float* note    = (const float*)d_in[0];
    const float* targets = (const float*)d_in[1];
    const float* tWih0   = (const float*)d_in[2];
    const float* tb0     = (const float*)d_in[4];
    const float* tWih1   = (const float*)d_in[5];
    const float* tb1     = (const float*)d_in[7];
    const float* nWih0   = (const float*)d_in[8];
    const float* nWhh0   = (const float*)d_in[9];
    const float* nb0     = (const float*)d_in[10];
    const float* nWih1   = (const float*)d_in[11];
    const float* nWhh1   = (const float*)d_in[12];
    const float* nb1     = (const float*)d_in[13];
    const float* outW    = (const float*)d_in[14];
    const float* outb    = (const float*)d_in[15];
    float* out = (float*)d_out;

    bf16 *p_ac0, *p_ac1, *p_ac2, *p_w0i, *p_w1i, *p_w2c;
    float *p_xw;
    cudaGetSymbolAddress((void**)&p_ac0, g_ac0);
    cudaGetSymbolAddress((void**)&p_ac1, g_ac1);
    cudaGetSymbolAddress((void**)&p_ac2, g_ac2);
    cudaGetSymbolAddress((void**)&p_w0i, g_w0i);
    cudaGetSymbolAddress((void**)&p_w1i, g_w1i);
    cudaGetSymbolAddress((void**)&p_w2c, g_w2c);
    cudaGetSymbolAddress((void**)&p_xw,  g_xw);

    build_ac0<<<(MM * 64) / 256, 256>>>(note);
    build_w0i<<<(768 * 64) / 256, 256>>>(tWih0);
    build_w1i<<<(768 * 256) / 256, 256>>>(tWih1);
    build_w2c<<<(512 * 256) / 256, 256>>>(nWih0);

    const int smemA = 128 * 100 * (int)sizeof(float);   // 51200 (dump >= staging)
    const int smemR = 128 * 132 * (int)sizeof(float);   // 67584
    cudaFuncSetAttribute((const void*)gemm_bfa<96, 6, true>,
                         cudaFuncAttributeMaxDynamicSharedMemorySize, smemA);
    cudaFuncSetAttribute((const void*)gemm_bfa<128, 8, false>,
                         cudaFuncAttributeMaxDynamicSharedMemorySize, smemR);

    // h1 = act(rnn_in' @ w0i'^T + b0)        (K'=192)
    gemm_bfa<96, 6, true><<<dim3(8, 384), 256, smemA>>>(p_ac0, 192, p_w0i,
                                                        tb0, p_ac1, nullptr);
    // feats = act(h1' @ w1i'^T + b1)         (K'=768)
    gemm_bfa<96, 6, true><<<dim3(8, 384), 256, smemA>>>(p_ac1, 768, p_w1i,
                                                        tb1, p_ac2, nullptr);
    // g_xw = feats' @ w2c'^T                 (K'=768, raw gates for the scan)
    gemm_bfa<128, 8, false><<<dim3(4, 384), 256, smemR>>>(p_ac2, 768, p_w2c,
                                                          nullptr, nullptr, p_xw);

    const int smemS = 22656 * (int)sizeof(float);  // 90624 B
    cudaFuncSetAttribute(scan_kernel, cudaFuncAttributeMaxDynamicSharedMemorySize, smemS);
    scan_kernel<<<128, 256, smemS>>>(targets, nWhh0, nb0, nWih1, nWhh1, nb1,
                                     outW, outb, out);
}